// round 13
// baseline (speedup 1.0000x reference)
#include <cuda_runtime.h>
#include <cuda_fp16.h>
#include <cstdint>

// out[src] += edge_attr[e] * x[dst]   (E=1.6M, N=100k, D=32)
// Inputs: edge_index int32 [2,E], edge_attr f32 [E], x f32 [N,32]
// Output: f32 [N,32]
//
// R13: scatter core unchanged (fp16 gather + f16x2 RED into 4 parity-split
// compact buffers — L2-byte-wall bound ~38us). Aux trimmed: prep converts
// only; combine sums buffers into out AND re-zeros them (steady-state
// invariant: g_acc is all-zero on entry to every launch, starting from BSS).

#define N_CAP  131072
#define NBUF   4

__device__ __half2 g_xh[N_CAP * 16];             // fp16 copy of x (row = 16 half2)
__device__ __half2 g_acc[NBUF * N_CAP * 16];     // flat; runtime stride n_nodes*16

__device__ __forceinline__ void red_add_h2(__half2* addr, __half2 v) {
    asm volatile("red.global.add.noftz.f16x2 [%0], %1;"
                 :: "l"(addr), "r"(*(unsigned int*)&v) : "memory");
}
__device__ __forceinline__ unsigned int ldcg_b32(const void* p) {
    unsigned int v;
    asm volatile("ld.global.cg.b32 %0, [%1];" : "=r"(v) : "l"(p));
    return v;
}
__device__ __forceinline__ void red_add_v4(float* addr, float4 v) {
    asm volatile("red.global.add.v4.f32 [%0], {%1, %2, %3, %4};"
                 :: "l"(addr), "f"(v.x), "f"(v.y), "f"(v.z), "f"(v.w)
                 : "memory");
}
__device__ __forceinline__ float4 ldcg_v4f(const float* p) {
    float4 v;
    asm volatile("ld.global.cg.v4.f32 {%0, %1, %2, %3}, [%4];"
                 : "=f"(v.x), "=f"(v.y), "=f"(v.z), "=f"(v.w)
                 : "l"(p));
    return v;
}

// ---- 1. prep: convert x -> fp16 (convert ONLY; zeroing lives in combine) --
__global__ void prep_kernel(const float* __restrict__ x, int nx4) {
    int i = blockIdx.x * blockDim.x + threadIdx.x;
    int stride = gridDim.x * blockDim.x;
    for (; i < nx4; i += stride) {
        float4 f = ((const float4*)x)[i];
        g_xh[i * 2]     = __floats2half2_rn(f.x, f.y);
        g_xh[i * 2 + 1] = __floats2half2_rn(f.z, f.w);
    }
}

// ---- 2. scatter: fp16 gather + f16x2 RED into buffer ((e>>1)&3) -----------
#define EDGES_PER_WARP 32

__global__ __launch_bounds__(256) void scatter_h2_kernel(
        const int* __restrict__ edge_index,
        const float* __restrict__ edge_attr,
        int E, int buf_stride) {          // buf_stride = n_nodes * 16 (half2)
    int lane = threadIdx.x & 31;
    int slot = lane >> 4;              // 0..1 : which edge in the pair
    int h    = lane & 15;              // 0..15: which half2 of the row
    int warp = (blockIdx.x * blockDim.x + threadIdx.x) >> 5;
    int base = warp * EDGES_PER_WARP;
    if (base >= E) return;

    bool full = (base + EDGES_PER_WARP <= E);

    #pragma unroll 8
    for (int g = 0; g < EDGES_PER_WARP / 2; g++) {
        int e = base + g * 2 + slot;
        if (!full && e >= E) continue;

        int   src = __ldg(&edge_index[e]);
        int   dst = __ldg(&edge_index[E + e]);
        float a   = __ldg(&edge_attr[e]);

        unsigned int hb = ldcg_b32(&g_xh[(long)dst * 16 + h]);  // 1 half2 = 4B
        float2 f = __half22float2(*(__half2*)&hb);
        __half2 hv = __floats2half2_rn(a * f.x, a * f.y);

        // (e>>1)&3: both edges of one warp instruction use the SAME buffer
        int buf = (e >> 1) & 3;
        red_add_h2(&g_acc[(long)buf * buf_stride + (long)src * 16 + h], hv);
    }
}

// ---- 3. combine: out = fp32 sum of the 4 buffers; re-zero buffers ---------
// n16 = n_nodes*16/4 uint4 units per buffer; bs16 = same stride in uint4.
__global__ void combine_kernel(float4* __restrict__ out, int n16, int bs16) {
    int i = blockIdx.x * blockDim.x + threadIdx.x;
    int stride = gridDim.x * blockDim.x;
    uint4* acc = (uint4*)g_acc;
    uint4 z = make_uint4(0u, 0u, 0u, 0u);
    for (; i < n16; i += stride) {
        float s[8];
        #pragma unroll
        for (int k = 0; k < 8; k++) s[k] = 0.f;
        #pragma unroll
        for (int b = 0; b < NBUF; b++) {
            uint4 a = acc[(long)b * bs16 + i];
            acc[(long)b * bs16 + i] = z;            // re-zero for next launch
            float2 f0 = __half22float2(*(__half2*)&a.x);
            float2 f1 = __half22float2(*(__half2*)&a.y);
            float2 f2 = __half22float2(*(__half2*)&a.z);
            float2 f3 = __half22float2(*(__half2*)&a.w);
            s[0] += f0.x; s[1] += f0.y; s[2] += f1.x; s[3] += f1.y;
            s[4] += f2.x; s[5] += f2.y; s[6] += f3.x; s[7] += f3.y;
        }
        out[i * 2]     = make_float4(s[0], s[1], s[2], s[3]);
        out[i * 2 + 1] = make_float4(s[4], s[5], s[6], s[7]);
    }
}

// ---- fallback (R4-style fp32 direct scatter) for oversize inputs ----------
__global__ void zero_out_kernel(float4* __restrict__ out, int n4) {
    int i = blockIdx.x * blockDim.x + threadIdx.x;
    int stride = gridDim.x * blockDim.x;
    float4 z = make_float4(0.f, 0.f, 0.f, 0.f);
    for (; i < n4; i += stride) out[i] = z;
}
__global__ __launch_bounds__(256) void scatter_f_kernel(
        const int* __restrict__ edge_index,
        const float* __restrict__ edge_attr,
        const float* __restrict__ x,
        float* __restrict__ out, int E) {
    int lane = threadIdx.x & 31;
    int slot = lane >> 3;
    int fofs = (lane & 7) << 2;
    int warp = (blockIdx.x * blockDim.x + threadIdx.x) >> 5;
    int base = warp * 32;
    if (base >= E) return;
    for (int i = 0; i < 8; i++) {
        int e = base + i * 4 + slot;
        if (e < E) {
            int src = __ldg(&edge_index[e]);
            int dst = __ldg(&edge_index[E + e]);
            float a = __ldg(&edge_attr[e]);
            float4 v = ldcg_v4f(x + (long)dst * 32 + fofs);
            v.x *= a; v.y *= a; v.z *= a; v.w *= a;
            red_add_v4(out + (long)src * 32 + fofs, v);
        }
    }
}

extern "C" void kernel_launch(void* const* d_in, const int* in_sizes, int n_in,
                              void* d_out, int out_size) {
    const int*   edge_index = (const int*)d_in[0];
    const float* edge_attr  = (const float*)d_in[1];
    const float* x          = (const float*)d_in[2];
    float*       out        = (float*)d_out;

    int E       = in_sizes[0] / 2;
    int nx      = in_sizes[2];
    int n_nodes = nx / 32;

    if (n_nodes <= N_CAP && (nx & 3) == 0 && out_size == nx) {
        int buf_stride = n_nodes * 16;            // half2 per buffer
        int nx4 = nx / 4;                         // float4 elems of x

        int pb = (nx4 + 255) / 256; if (pb > 4096) pb = 4096;
        prep_kernel<<<pb, 256>>>(x, nx4);

        int warps = (E + EDGES_PER_WARP - 1) / EDGES_PER_WARP;
        int blocks = (warps * 32 + 255) / 256;
        scatter_h2_kernel<<<blocks, 256>>>(edge_index, edge_attr, E, buf_stride);

        int n16  = buf_stride / 4;                // uint4 units per buffer
        int bs16 = buf_stride / 4;
        int cb = (n16 + 255) / 256; if (cb > 8192) cb = 8192;
        combine_kernel<<<cb, 256>>>((float4*)out, n16, bs16);
    } else {
        int no4 = out_size / 4;
        int zb = (no4 + 255) / 256; if (zb > 8192) zb = 8192;
        zero_out_kernel<<<zb, 256>>>((float4*)out, no4);
        int warps = (E + 31) / 32;
        int blocks = (warps * 32 + 255) / 256;
        scatter_f_kernel<<<blocks, 256>>>(edge_index, edge_attr, x, out, E);
    }
}

// round 15
// speedup vs baseline: 1.4773x; 1.4773x over previous
#include <cuda_runtime.h>
#include <cstdint>

// out[src] += edge_attr[e] * x[dst]   (E=1.6M, N=100k, D=32)
// Inputs: edge_index int32 [2,E], edge_attr f32 [E], x f32 [N,32]
// Output: f32 [N,32]
//
// R14b (resubmit after infra failure): direct fp32 scatter (proven fastest
// family, ~42.6us scatter = L2 RMW-service floor). R3 shape (4 edge-slots x
// 8 lanes, LDG.128 gather + RED.128) with 64 edges/warp (half the CTAs) and
// 8-edge metadata batching.

__global__ void zero_out_kernel(float4* __restrict__ out, int n4) {
    int i = blockIdx.x * blockDim.x + threadIdx.x;
    int stride = gridDim.x * blockDim.x;
    float4 z = make_float4(0.f, 0.f, 0.f, 0.f);
    for (; i < n4; i += stride) out[i] = z;
}

__device__ __forceinline__ void red_add_v4(float* addr, float4 v) {
    asm volatile("red.global.add.v4.f32 [%0], {%1, %2, %3, %4};"
                 :: "l"(addr), "f"(v.x), "f"(v.y), "f"(v.z), "f"(v.w)
                 : "memory");
}

__device__ __forceinline__ float4 ldcg_v4f(const float* p) {
    float4 v;
    asm volatile("ld.global.cg.v4.f32 {%0, %1, %2, %3}, [%4];"
                 : "=f"(v.x), "=f"(v.y), "=f"(v.z), "=f"(v.w)
                 : "l"(p));
    return v;
}

#define EDGES_PER_WARP 64

__global__ __launch_bounds__(256) void scatter_kernel(
        const int* __restrict__ edge_index,
        const float* __restrict__ edge_attr,
        const float* __restrict__ x,
        float* __restrict__ out,
        int E) {
    int lane = threadIdx.x & 31;
    int slot = lane >> 3;            // 0..3 : which edge in the group of 4
    int fofs = (lane & 7) << 2;      // 0..28: feature offset (floats)
    int warp = (blockIdx.x * blockDim.x + threadIdx.x) >> 5;
    int base = warp * EDGES_PER_WARP;
    if (base >= E) return;

    if (base + EDGES_PER_WARP <= E) {
        #pragma unroll
        for (int g = 0; g < EDGES_PER_WARP / 8; g++) {      // 8 groups of 8
            int e0 = base + g * 8 + slot;

            // batch metadata for 8 edges (2 sub-groups of 4)
            int   src0 = __ldg(&edge_index[e0]);
            int   src1 = __ldg(&edge_index[e0 + 4]);
            int   dst0 = __ldg(&edge_index[E + e0]);
            int   dst1 = __ldg(&edge_index[E + e0 + 4]);
            float a0   = __ldg(&edge_attr[e0]);
            float a1   = __ldg(&edge_attr[e0 + 4]);

            // two independent gathers in flight
            float4 v0 = ldcg_v4f(x + (long)dst0 * 32 + fofs);
            float4 v1 = ldcg_v4f(x + (long)dst1 * 32 + fofs);

            v0.x *= a0; v0.y *= a0; v0.z *= a0; v0.w *= a0;
            red_add_v4(out + (long)src0 * 32 + fofs, v0);
            v1.x *= a1; v1.y *= a1; v1.z *= a1; v1.w *= a1;
            red_add_v4(out + (long)src1 * 32 + fofs, v1);
        }
    } else {
        for (int i = 0; i < EDGES_PER_WARP / 4; i++) {
            int e = base + i * 4 + slot;
            if (e < E) {
                int src = __ldg(&edge_index[e]);
                int dst = __ldg(&edge_index[E + e]);
                float a = __ldg(&edge_attr[e]);
                float4 v = ldcg_v4f(x + (long)dst * 32 + fofs);
                v.x *= a; v.y *= a; v.z *= a; v.w *= a;
                red_add_v4(out + (long)src * 32 + fofs, v);
            }
        }
    }
}

extern "C" void kernel_launch(void* const* d_in, const int* in_sizes, int n_in,
                              void* d_out, int out_size) {
    const int*   edge_index = (const int*)d_in[0];
    const float* edge_attr  = (const float*)d_in[1];
    const float* x          = (const float*)d_in[2];
    float*       out        = (float*)d_out;

    int E = in_sizes[0] / 2;

    // zero the (poisoned) output
    int n4 = out_size / 4;
    int zt = 256;
    int zb = (n4 + zt - 1) / zt;
    if (zb > 8192) zb = 8192;
    zero_out_kernel<<<zb, zt>>>((float4*)out, n4);

    // 64 edges per warp
    int warps   = (E + EDGES_PER_WARP - 1) / EDGES_PER_WARP;
    int threads = 256;                       // 8 warps/block
    int blocks  = (warps * 32 + threads - 1) / threads;
    scatter_kernel<<<blocks, threads>>>(edge_index, edge_attr, x, out, E);
}